// round 4
// baseline (speedup 1.0000x reference)
#include <cuda_runtime.h>
#include <cuda_bf16.h>

// Scratch (allocation-free rule: __device__ globals)
__device__ float g_SC[1024];               // S_C[k*4+l]
__device__ float g_SXp[2][128 * 64];       // row-split partials of S_x[b*64+h*8+w]

// ---------------------------------------------------------------------------
// Kernel 1 (fused reduce): 2176 blocks x 192 threads.
//   blocks [0,128):    full reduce of C columns -> g_SC.
//   blocks [128,2176): sumX half-block: (b, h1, half). 16 rows (r = h1+8q,
//                      q in [16*half, 16*half+16)) x 768 floats binned into
//                      8 w2 sums via bin-safe strides (multiples of 24 floats).
// ---------------------------------------------------------------------------
__global__ void reduce_kernel(const float* __restrict__ x,
                              const float* __restrict__ C) {
    __shared__ float sm[768];              // also viewed as float4 sm4[192]
    const int t = threadIdx.x;             // 0..191

    if (blockIdx.x < 128) {
        // ---------------- sumC ----------------
        float4* sm4 = (float4*)sm;         // [c(2)][rg(96)]
        const int cid = blockIdx.x;
        const int c  = t & 1;
        const int rg = t >> 1;             // 0..95
        const int c4 = 2 * cid + c;
        const float4* __restrict__ C4 = (const float4*)C;  // 256 f4 per row
        float4 acc = make_float4(0.f, 0.f, 0.f, 0.f);
#pragma unroll 8
        for (int q = 0; q < 32; ++q) {
            float4 v = C4[(rg + 96 * q) * 256 + c4];
            acc.x += v.x; acc.y += v.y; acc.z += v.z; acc.w += v.w;
        }
        sm4[c * 96 + rg] = acc;
        __syncthreads();
        for (int s = 48; s >= 3; s >>= 1) {
            if (rg < s) {
                float4 a  = sm4[c * 96 + rg];
                float4 bv = sm4[c * 96 + rg + s];
                a.x += bv.x; a.y += bv.y; a.z += bv.z; a.w += bv.w;
                sm4[c * 96 + rg] = a;
            }
            __syncthreads();
        }
        if (rg == 0) {
            float4 a0 = sm4[c * 96 + 0];
            float4 a1 = sm4[c * 96 + 1];
            float4 a2 = sm4[c * 96 + 2];
            float4 r;
            r.x = a0.x + a1.x + a2.x;
            r.y = a0.y + a1.y + a2.y;
            r.z = a0.z + a1.z + a2.z;
            r.w = a0.w + a1.w + a2.w;
            ((float4*)g_SC)[2 * cid + c] = r;
        }
        return;
    }

    // ---------------- sumX (half-block) ----------------
    const int blk  = blockIdx.x - 128;     // 0..2047
    const int half = blk & 1;
    const int bh   = blk >> 1;             // b*8 + h1
    const int b    = bh >> 3;
    const int h1   = bh & 7;

    const float4* __restrict__ x4 = (const float4*)x;   // 192 f4 per row
    long base = (long)b * 49152 + (long)h1 * 192 + (long)half * 16 * 1536 + t;

    float4 acc = make_float4(0.f, 0.f, 0.f, 0.f);
#pragma unroll 8
    for (int q = 0; q < 16; ++q) {
        float4 v = x4[base + (long)q * 1536];            // +8 rows per step
        acc.x += v.x; acc.y += v.y; acc.z += v.z; acc.w += v.w;
    }
    sm[4 * t + 0] = acc.x;
    sm[4 * t + 1] = acc.y;
    sm[4 * t + 2] = acc.z;
    sm[4 * t + 3] = acc.w;
    __syncthreads();

    // strides that are multiples of 24 floats preserve the w2 bin
    sm[t]       += sm[t + 384];
    sm[t + 192] += sm[t + 576];
    __syncthreads();
    sm[t] += sm[t + 192];
    __syncthreads();
    if (t < 96) sm[t] += sm[t + 96];
    __syncthreads();
    if (t < 48) sm[t] += sm[t + 48];
    __syncthreads();
    if (t < 24) sm[t] += sm[t + 24];
    __syncthreads();
    if (t < 8) {
        float s = sm[3 * t] + sm[3 * t + 1] + sm[3 * t + 2];
        g_SXp[half][bh * 8 + t] = s;       // = b*64 + h1*8 + w2
    }
}

// ---------------------------------------------------------------------------
// Kernel 2 (expand): out[b,kl,hw] = S_C[kl] * (S_xA[b,hw] + S_xB[b,hw]).
// 2048 blocks x 256 threads; each block owns 4096 consecutive floats (one b,
// 64 consecutive kl, all 64 hw). Stores are STREAMING (__stcs, evict-first)
// so out does NOT evict x/C from L2 -> x stays L2-resident across replays.
// ---------------------------------------------------------------------------
__global__ void expand_kernel(float* __restrict__ out) {
    __shared__ float  sc_s[64];
    __shared__ float4 sx_s[16];
    const int t   = threadIdx.x;
    const int blk = blockIdx.x;            // 0..2047
    const int b   = blk >> 4;              // 16 blocks per b
    const int kl0 = (blk & 15) * 64;

    if (t < 64) {
        sc_s[t] = g_SC[kl0 + t];
    } else if (t < 80) {
        const int i = t - 64;
        float4 a = ((const float4*)g_SXp[0])[b * 16 + i];
        float4 c = ((const float4*)g_SXp[1])[b * 16 + i];
        a.x += c.x; a.y += c.y; a.z += c.z; a.w += c.w;
        sx_s[i] = a;
    }
    __syncthreads();

    float4* out4 = (float4*)out + (long)blk * 1024;
#pragma unroll
    for (int i = 0; i < 4; ++i) {
        const int j = t + 256 * i;         // 0..1023 (float4 within block)
        const float  sc = sc_s[j >> 4];
        const float4 sx = sx_s[j & 15];
        float4 r;
        r.x = sc * sx.x; r.y = sc * sx.y; r.z = sc * sx.z; r.w = sc * sx.w;
        __stcs(&out4[j], r);               // streaming store: evict-first in L2
    }
}

// ---------------------------------------------------------------------------
extern "C" void kernel_launch(void* const* d_in, const int* in_sizes, int n_in,
                              void* d_out, int out_size) {
    const float* x = (const float*)d_in[0];  // [128,256,256,3]
    const float* C = (const float*)d_in[1];  // [768,4,256,4]
    float* out = (float*)d_out;              // [128,256,4,8,8]

    reduce_kernel<<<2176, 192>>>(x, C);
    expand_kernel<<<2048, 256>>>(out);
}